// round 13
// baseline (speedup 1.0000x reference)
#include <cuda_runtime.h>
#include <math.h>

typedef unsigned long long u64;
typedef unsigned short u16;
typedef unsigned char u8;

#define NN 4096
#define MM 20
#define HH 16
#define NX 32
#define NY 18
#define NLAB 3
#define NCELL (NLAB*NX*NY)   /* 1728 */
#define CAP 64
#define CAPC 28
#define SCAP 24576           /* shared CSR capacity (entries) */
#define PI_F 3.14159274101257324f
#define QPI_F 0.785398185253143311f
#define COND 0.2f
#define IOUT 0.3f

// ---------------- global scratch (no allocations allowed) ----------------
__device__ u64    g_keysg[NN];        // sorted keys (pos -> key|idx)
__device__ int    g_vt;
__device__ float  g_b7[NN*7];
__device__ float4 g_bev[NN];
__device__ float  g_area[NN];
__device__ int    g_cellid[NN];
__device__ int    g_cellcnt[NCELL];
__device__ u16    g_cellbox[NCELL*CAPC];
__device__ u16    g_pred[NN*CAP];     // rows 128B-aligned (CAP*2 = 128)
__device__ u16    g_succ[NN*CAP];
__device__ int    g_npred[NN], g_nsucc[NN];
__device__ u8     g_sts[NN];          // 1=kept 2=suppressed 3=invalid
__device__ u16    g_sby[NN];          // suppressor (self if kept, 0xFFFF invalid)

// ---------------- warp-shuffle inclusive scan ----------------
__device__ __forceinline__ int warp_iscan(int v, int lane) {
    #pragma unroll
    for (int o = 1; o < 32; o <<= 1) {
        int n = __shfl_up_sync(0xFFFFFFFFu, v, o);
        if (lane >= o) v += n;
    }
    return v;
}

// ============ 1) single-block sort: reads scores, writes sorted keys ============
#define OFF_KEYS  0         /* u64[4096] 32KB */
#define OFF_CNT   32768     /* int[4096] 16KB */
#define OFF_START 49152     /* int[4096] 16KB */
#define OFF_TEMP  65536     /* int[32]  128B  */
#define SMEM_A    65664

__global__ __launch_bounds__(1024) void k_sort(const float* __restrict__ ps)
{
    extern __shared__ char sm[];
    u64* keys   = (u64*)(sm + OFF_KEYS);
    int* bcnt   = (int*)(sm + OFF_CNT);
    int* bstart = (int*)(sm + OFF_START);
    int* temp   = (int*)(sm + OFF_TEMP);

    const int t = threadIdx.x;
    const int lane = t & 31;
    const int wid  = t >> 5;
    const int base = t * 4;

    for (int c = t; c < NCELL; c += 1024) g_cellcnt[c] = 0;
    for (int b = t; b < NN; b += 1024) bcnt[b] = 0;
    __syncthreads();

    unsigned keyv[4]; int bk[4]; int invc = 0;
    #pragma unroll
    for (int k = 0; k < 4; k++) {
        int i = base + k;
        float f = ps[i];
        if (f > COND) {
            unsigned u = __float_as_uint(f) | 0x80000000u;
            keyv[k] = ~u;                           // ascending key == descending f
            int b = 4096 - (int)(f * 4096.0f);
            b = min(max(b, 0), 4095);
            bk[k] = b;
            atomicAdd(&bcnt[b], 1);
        } else { bk[k] = -1; invc++; }
    }
    __syncthreads();

    // packed scan: low 16 = bucket-count sums, high 16 = invalid counts
    int myc[4]; int s0 = 0;
    #pragma unroll
    for (int k = 0; k < 4; k++) { myc[k] = bcnt[base + k]; s0 += myc[k]; }
    int packed = s0 | (invc << 16);
    int incl = warp_iscan(packed, lane);
    if (lane == 31) temp[wid] = incl;
    __syncthreads();
    if (t < 32) temp[t] = warp_iscan(temp[t], t);
    __syncthreads();
    int pre = (wid > 0) ? temp[wid - 1] : 0;
    incl += pre;
    int tot = temp[31];
    int vt  = tot & 0xFFFF;
    if (t == 0) g_vt = vt;
    int excl = incl - packed;
    int run     = excl & 0xFFFF;
    int invPre  = (excl >> 16) & 0xFFFF;
    #pragma unroll
    for (int k = 0; k < 4; k++) { bstart[base + k] = run; run += myc[k]; }
    int invBase = vt + invPre;
    __syncthreads();

    // scatter
    int li = 0;
    #pragma unroll
    for (int k = 0; k < 4; k++) {
        int i = base + k;
        if (bk[k] >= 0) {
            int pos = atomicAdd(&bstart[bk[k]], 1);
            keys[pos] = ((u64)keyv[k] << 32) | (unsigned)i;
        } else {
            keys[invBase + li] = 0xFFFFFFFF00000000ull | (unsigned)i;
            li++;
        }
    }
    __syncthreads();

    // per-bucket insertion sort (segment = [bstart[b]-bcnt[b], bstart[b]))
    for (int b = t; b < NN; b += 1024) {
        int c = bcnt[b];
        if (c > 1) {
            int s = bstart[b] - c;
            for (int a = 1; a < c; a++) {
                u64 v = keys[s + a];
                int q = a - 1;
                while (q >= 0 && keys[s + q] > v) { keys[s + q + 1] = keys[s + q]; q--; }
                keys[s + q + 1] = v;
            }
        }
    }
    __syncthreads();

    // write sorted keys coalesced
    #pragma unroll
    for (int k = 0; k < 4; k++) {
        int i = base + k;
        g_keysg[i] = keys[i];
    }
}

// ============ 2) multi-block gather: one thread per SORTED position ============
__global__ __launch_bounds__(256) void k_gather(
    const float* __restrict__ pb, const float* __restrict__ ps,
    const int* __restrict__ pl, float* __restrict__ out)
{
    int i = blockIdx.x * 256 + threadIdx.x;   // sorted position
    if (i >= NN) return;
    int idx = (int)(g_keysg[i] & 0xFFFFFFFFu);

    float b[9];
    #pragma unroll
    for (int c = 0; c < 9; c++) b[c] = pb[idx*9 + c];
    #pragma unroll
    for (int c = 0; c < 7; c++) { g_b7[i*7 + c] = b[c]; out[i*9 + c] = b[c]; }
    out[i*9 + 7] = b[7];
    out[i*9 + 8] = b[8];
    out[NN*9  + i] = ps[idx];
    int lab = pl[idx];
    out[NN*10 + i] = (float)lab;

    float h   = b[6];
    float ang = h - floorf(h / PI_F + 0.5f) * PI_F;
    bool  sw  = fabsf(ang) >= QPI_F;
    float dx  = sw ? b[4] : b[3];
    float dy  = sw ? b[3] : b[4];
    float4 bv;
    bv.x = b[0] - dx * 0.5f;
    bv.y = b[1] - dy * 0.5f;
    bv.z = b[0] + dx * 0.5f;
    bv.w = b[1] + dy * 0.5f;
    g_bev[i]  = bv;
    g_area[i] = dx * dy;

    int cx = (int)floorf((b[0] + 70.0f) * (1.0f / 4.5f)); cx = min(max(cx, 0), NX-1);
    int cy = (int)floorf((b[1] + 40.0f) * (1.0f / 4.5f)); cy = min(max(cy, 0), NY-1);
    int cell = (lab * NY + cy) * NX + cx;
    g_cellid[i] = cell;
    int pos = atomicAdd(&g_cellcnt[cell], 1);
    if (pos < CAPC) g_cellbox[cell*CAPC + pos] = (u16)i;
}

// ============ 3) multi-block: build overlap pred/succ lists ============
__global__ __launch_bounds__(256) void k_build() {
    int i = blockIdx.x * 256 + threadIdx.x;
    if (i >= NN) return;
    float4 a = g_bev[i];
    float aa = g_area[i];
    int cell = g_cellid[i];
    int cx = cell % NX, cy = (cell / NX) % NY, lab = cell / (NX * NY);
    int np = 0, ns = 0;
    for (int dy = -1; dy <= 1; dy++) {
        int yy = cy + dy; if (yy < 0 || yy >= NY) continue;
        for (int dx = -1; dx <= 1; dx++) {
            int xx = cx + dx; if (xx < 0 || xx >= NX) continue;
            int c2 = (lab * NY + yy) * NX + xx;
            int cnt2 = min(g_cellcnt[c2], CAPC);
            for (int p = 0; p < cnt2; p++) {
                int j = g_cellbox[c2*CAPC + p];
                if (j == i) continue;
                float4 bb = g_bev[j];
                float ix = fminf(a.z, bb.z) - fmaxf(a.x, bb.x);
                float iy = fminf(a.w, bb.w) - fmaxf(a.y, bb.y);
                float inter = fmaxf(ix, 0.0f) * fmaxf(iy, 0.0f);
                float uni   = aa + g_area[j] - inter;
                if (inter > IOUT * fmaxf(uni, 1e-6f)) {
                    if (j < i) { if (np < CAP) g_pred[i*CAP + np++] = (u16)j; }
                    else       { if (ns < CAP) g_succ[i*CAP + ns++] = (u16)j; }
                }
            }
        }
    }
    for (int a2 = 1; a2 < ns; a2++) {
        u16 v = g_succ[i*CAP + a2];
        int b = a2 - 1;
        while (b >= 0 && g_succ[i*CAP + b] > v) { g_succ[i*CAP + b + 1] = g_succ[i*CAP + b]; b--; }
        g_succ[i*CAP + b + 1] = v;
    }
    g_npred[i] = np;
    g_nsucc[i] = ns;
}

// ============ 4) single-block: fixpoint + suppby (publish sts/sby) ============
#define F_OFFS  0           /* int[4097] -> pad to 16392 */
#define F_PD    16392       /* u16[SCAP] 49152 */
#define F_STS   65544       /* u8[4096]  4096 */
#define F_FL0   69640       /* u16[4096] 8192 */
#define F_FL1   77832       /* u16[4096] 8192 */
#define F_TMP   86024       /* int[32]   128  */
#define SMEM_F  86152

__global__ __launch_bounds__(1024) void k_fix(float* __restrict__ out) {
    extern __shared__ char sm[];
    int* offs = (int*)(sm + F_OFFS);
    u16* pd   = (u16*)(sm + F_PD);
    u8*  sts  = (u8*)(sm + F_STS);
    u16* fl0  = (u16*)(sm + F_FL0);
    u16* fl1  = (u16*)(sm + F_FL1);
    int* temp = (int*)(sm + F_TMP);
    __shared__ int s_useg, s_nf, s_nn;
    volatile u8* st = sts;
    const int t = threadIdx.x;
    const int lane = t & 31;
    const int wid  = t >> 5;
    const int base = t * 4;
    const int vt = g_vt;

    // CSR offsets via warp-shuffle scan
    int np4[4]; int s0 = 0;
    #pragma unroll
    for (int k = 0; k < 4; k++) { np4[k] = g_npred[base + k]; s0 += np4[k]; }
    int incl = warp_iscan(s0, lane);
    if (lane == 31) temp[wid] = incl;
    __syncthreads();
    if (t < 32) temp[t] = warp_iscan(temp[t], t);
    __syncthreads();
    int run = incl + ((wid > 0) ? temp[wid - 1] : 0) - s0;
    #pragma unroll
    for (int k = 0; k < 4; k++) { offs[base + k] = run; run += np4[k]; }
    if (t == 1023) offs[NN] = run;
    if (t == 0) { s_useg = (temp[31] > SCAP) ? 1 : 0; s_nf = vt; }
    __syncthreads();
    const int useg = s_useg;
    if (!useg) {
        // vectorized copy: u64 loads (4 u16 entries per LDG); rows 128B-aligned
        #pragma unroll
        for (int k = 0; k < 4; k++) {
            int i = base + k, o = offs[i], np = np4[k];
            const u64* src = (const u64*)&g_pred[i*CAP];
            for (int p = 0; p < np; p += 4) {
                u64 v = src[p >> 2];
                pd[o + p] = (u16)v;
                if (p + 1 < np) pd[o + p + 1] = (u16)(v >> 16);
                if (p + 2 < np) pd[o + p + 2] = (u16)(v >> 32);
                if (p + 3 < np) pd[o + p + 3] = (u16)(v >> 48);
            }
        }
    }
    for (int i = t; i < NN; i += 1024) sts[i] = (i < vt) ? 0 : 3;
    for (int i = t; i < vt; i += 1024) fl0[i] = (u16)i;
    __syncthreads();

    // frontier-compacted chaotic relaxation
    u16* cur = fl0; u16* nxt = fl1;
    for (int round = 0; round < NN; round++) {
        int nf = s_nf;
        if (nf <= 0) break;
        if (t == 0) s_nn = 0;
        __syncthreads();
        for (int k = t; k < nf; k += 1024) {
            int i = cur[k];
            int o = offs[i], np = offs[i+1] - o;
            bool anyK = false, allS = true;
            for (int p = 0; p < np; p++) {
                int j = useg ? (int)g_pred[i*CAP + p] : (int)pd[o + p];
                u8 s = st[j];
                anyK |= (s == 1);
                allS &= (s >= 2);
            }
            if (anyK)      st[i] = 2;
            else if (allS) st[i] = 1;
            else { int pos = atomicAdd(&s_nn, 1); nxt[pos] = (u16)i; }
        }
        __syncthreads();
        if (t == 0) s_nf = s_nn;
        u16* tmpp = cur; cur = nxt; nxt = tmpp;
        __syncthreads();
    }

    // publish status, suppby, keep flags
    for (int i = t; i < NN; i += 1024) {
        u8 s = sts[i];
        g_sts[i] = s;
        out[NN*11 + i] = (s == 1) ? 1.0f : 0.0f;
        u16 sb;
        if (s == 1) sb = (u16)i;
        else if (s == 3) sb = 0xFFFF;
        else {
            int o = offs[i], np = offs[i+1] - o;
            int best = 0xFFFF;
            for (int p = 0; p < np; p++) {
                int q = useg ? (int)g_pred[i*CAP + p] : (int)pd[o + p];
                if (sts[q] == 1 && q < best) best = q;
            }
            sb = (u16)best;
        }
        g_sby[i] = sb;
    }
}

// ============ 5) merge MLP: thread per (sorted idx, channel), self-built cluster ============
__global__ __launch_bounds__(256) void k_merge(
    const float* __restrict__ w1, const float* __restrict__ b1,
    const float* __restrict__ w2, const float* __restrict__ b2,
    const float* __restrict__ w3, const float* __restrict__ b3,
    float* __restrict__ out)
{
    __shared__ float s_w1[MM*HH], s_w2[HH*HH], s_w3[HH], s_b1[HH], s_b2[HH], s_b3;
    const int t = threadIdx.x;
    for (int k = t; k < MM*HH; k += 256) s_w1[k] = w1[k];
    for (int k = t; k < HH*HH; k += 256) s_w2[k] = w2[k];
    if (t < HH) { s_w3[t] = w3[t]; s_b1[t] = b1[t]; s_b2[t] = b2[t]; }
    if (t == 0) s_b3 = b3[0];
    __syncthreads();

    int gt = blockIdx.x * 256 + t;
    int i = gt >> 3;
    int c = gt & 7;
    if (c >= 7 || i >= NN) return;
    if (g_sts[i] != 1) return;

    // rebuild member list (succ sorted ascending; member iff suppressed-by == i)
    int ns = g_nsucc[i];
    u16 mem[MM];
    mem[0] = (u16)i;
    int cnt = 1, total = 1;
    for (int a = 0; a < ns; a++) {
        int j = g_succ[i*CAP + a];
        if ((int)g_sby[j] == i) { total++; if (cnt < MM) mem[cnt++] = (u16)j; }
    }
    if (total <= 1) return;   // baseline row already written by k_gather

    // prefetch member channel values (independent loads)
    float xv[MM];
    #pragma unroll
    for (int m = 0; m < MM; m++) if (m < cnt) xv[m] = g_b7[(int)mem[m]*7 + c];

    float h1[HH];
    #pragma unroll
    for (int h = 0; h < HH; h++) h1[h] = s_b1[h];
    #pragma unroll
    for (int m = 0; m < MM; m++) {
        if (m < cnt) {
            float v = xv[m];
            #pragma unroll
            for (int h = 0; h < HH; h++) h1[h] += v * s_w1[m*HH + h];
        }
    }
    #pragma unroll
    for (int h = 0; h < HH; h++) h1[h] = fmaxf(h1[h], 0.0f);
    float h2[HH];
    #pragma unroll
    for (int q = 0; q < HH; q++) h2[q] = s_b2[q];
    #pragma unroll
    for (int h = 0; h < HH; h++) {
        float v = h1[h];
        #pragma unroll
        for (int q = 0; q < HH; q++) h2[q] += v * s_w2[h*HH + q];
    }
    float acc = s_b3;
    #pragma unroll
    for (int q = 0; q < HH; q++) acc += fmaxf(h2[q], 0.0f) * s_w3[q];

    if (c >= 3 && c <= 5) acc = fmaxf(acc, 1e-5f);
    out[i*9 + c] = acc;
}

extern "C" void kernel_launch(void* const* d_in, const int* in_sizes, int n_in,
                              void* d_out, int out_size) {
    const float* pb = (const float*)d_in[0];
    const float* ps = (const float*)d_in[1];
    const int*   pl = (const int*)  d_in[2];
    const float* w1 = (const float*)d_in[3];
    const float* b1 = (const float*)d_in[4];
    const float* w2 = (const float*)d_in[5];
    const float* b2 = (const float*)d_in[6];
    const float* w3 = (const float*)d_in[7];
    const float* b3 = (const float*)d_in[8];
    float* out = (float*)d_out;

    cudaFuncSetAttribute(k_sort, cudaFuncAttributeMaxDynamicSharedMemorySize, SMEM_A);
    cudaFuncSetAttribute(k_fix,  cudaFuncAttributeMaxDynamicSharedMemorySize, SMEM_F);
    k_sort<<<1, 1024, SMEM_A>>>(ps);
    k_gather<<<16, 256>>>(pb, ps, pl, out);
    k_build<<<16, 256>>>();
    k_fix<<<1, 1024, SMEM_F>>>(out);
    k_merge<<<128, 256>>>(w1, b1, w2, b2, w3, b3, out);
}

// round 15
// speedup vs baseline: 1.0192x; 1.0192x over previous
#include <cuda_runtime.h>
#include <math.h>

typedef unsigned long long u64;
typedef unsigned short u16;
typedef unsigned char u8;

#define NN 4096
#define MM 20
#define HH 16
#define NX 32
#define NY 18
#define NLAB 3
#define NCELL (NLAB*NX*NY)   /* 1728 */
#define CAP 64
#define CAPC 28
#define PI_F 3.14159274101257324f
#define QPI_F 0.785398185253143311f
#define COND 0.2f
#define IOUT 0.3f

// ---------------- global scratch (no allocations allowed) ----------------
__device__ int    g_rank[NN];         // original idx -> sorted pos
__device__ int    g_vt;
__device__ float  g_b7[NN*7];         // sorted space
__device__ float4 g_bev[NN];          // ORIGINAL index space
__device__ float  g_area[NN];         // original space
__device__ int    g_cellid[NN];       // original space
__device__ int    g_cellcnt[NCELL];   // zeroed at end of k_merge (and initially)
__device__ u16    g_cellbox[NCELL*CAPC];  // original indices
__device__ u16    g_pred[NN*CAP];     // sorted space, entries = ranks, ASC sorted
__device__ u16    g_succ[NN*CAP];     // sorted space, entries = ranks, ASC sorted
__device__ int    g_npred[NN], g_nsucc[NN];
__device__ u8     g_sts[NN];          // 1=kept 2=suppressed 3=invalid
__device__ u16    g_sby[NN];          // suppressor (self if kept, 0xFFFF invalid)

// ---------------- warp-shuffle inclusive scan ----------------
__device__ __forceinline__ int warp_iscan(int v, int lane) {
    #pragma unroll
    for (int o = 1; o < 32; o <<= 1) {
        int n = __shfl_up_sync(0xFFFFFFFFu, v, o);
        if (lane >= o) v += n;
    }
    return v;
}

// ============ 1) fused: block 0 sorts (-> g_rank), blocks 1..16 prep cells ============
#define OFF_KEYS  0         /* u64[4096] 32KB */
#define OFF_CNT   32768     /* int[4096] 16KB */
#define OFF_START 49152     /* int[4096] 16KB */
#define OFF_TEMP  65536     /* int[32]  128B  */
#define SMEM_A    65664

__global__ __launch_bounds__(1024) void k_sortprep(
    const float* __restrict__ ps, const float* __restrict__ pb)
{
    extern __shared__ char sm[];
    const int t = threadIdx.x;
    const int bid = blockIdx.x;

    if (bid >= 1) {
        // ---- prep: original-index space; independent of the sort ----
        if (t < 256) {
            int idx = (bid - 1) * 256 + t;
            float b0 = pb[idx*9 + 0];
            float b1 = pb[idx*9 + 1];
            float b3 = pb[idx*9 + 3];
            float b4 = pb[idx*9 + 4];
            float b6 = pb[idx*9 + 6];
            float ang = b6 - floorf(b6 / PI_F + 0.5f) * PI_F;
            bool  sw  = fabsf(ang) >= QPI_F;
            float dx  = sw ? b4 : b3;
            float dy  = sw ? b3 : b4;
            float4 bv;
            bv.x = b0 - dx * 0.5f;
            bv.y = b1 - dy * 0.5f;
            bv.z = b0 + dx * 0.5f;
            bv.w = b1 + dy * 0.5f;
            g_bev[idx]  = bv;
            g_area[idx] = dx * dy;
            int cx = (int)floorf((b0 + 70.0f) * (1.0f / 4.5f)); cx = min(max(cx, 0), NX-1);
            int cy = (int)floorf((b1 + 40.0f) * (1.0f / 4.5f)); cy = min(max(cy, 0), NY-1);
            // label needed for cell: load it
            // (pl passed via ps? no — labels loaded in k_build for out; here we need it for cell)
            // NOTE: label load below
        }
        return;   // replaced below — see k_prep note
    }

    // ---- block 0: bucket counting sort ----
    u64* keys   = (u64*)(sm + OFF_KEYS);
    int* bcnt   = (int*)(sm + OFF_CNT);
    int* bstart = (int*)(sm + OFF_START);
    int* temp   = (int*)(sm + OFF_TEMP);
    const int lane = t & 31;
    const int wid  = t >> 5;
    const int base = t * 4;

    for (int b = t; b < NN; b += 1024) bcnt[b] = 0;
    __syncthreads();

    unsigned keyv[4]; int bk[4]; int invc = 0;
    #pragma unroll
    for (int k = 0; k < 4; k++) {
        int i = base + k;
        float f = ps[i];
        if (f > COND) {
            unsigned u = __float_as_uint(f) | 0x80000000u;
            keyv[k] = ~u;                           // ascending key == descending f
            int b = 4096 - (int)(f * 4096.0f);
            b = min(max(b, 0), 4095);
            bk[k] = b;
            atomicAdd(&bcnt[b], 1);
        } else { bk[k] = -1; invc++; }
    }
    __syncthreads();

    // packed scan: low 16 = bucket-count sums, high 16 = invalid counts
    int myc[4]; int s0 = 0;
    #pragma unroll
    for (int k = 0; k < 4; k++) { myc[k] = bcnt[base + k]; s0 += myc[k]; }
    int packed = s0 | (invc << 16);
    int incl = warp_iscan(packed, lane);
    if (lane == 31) temp[wid] = incl;
    __syncthreads();
    if (t < 32) temp[t] = warp_iscan(temp[t], t);
    __syncthreads();
    int pre = (wid > 0) ? temp[wid - 1] : 0;
    incl += pre;
    int tot = temp[31];
    int vt  = tot & 0xFFFF;
    if (t == 0) g_vt = vt;
    int excl = incl - packed;
    int run     = excl & 0xFFFF;
    int invPre  = (excl >> 16) & 0xFFFF;
    #pragma unroll
    for (int k = 0; k < 4; k++) { bstart[base + k] = run; run += myc[k]; }
    int invBase = vt + invPre;
    __syncthreads();

    // scatter
    int li = 0;
    #pragma unroll
    for (int k = 0; k < 4; k++) {
        int i = base + k;
        if (bk[k] >= 0) {
            int pos = atomicAdd(&bstart[bk[k]], 1);
            keys[pos] = ((u64)keyv[k] << 32) | (unsigned)i;
        } else {
            keys[invBase + li] = 0xFFFFFFFF00000000ull | (unsigned)i;
            li++;
        }
    }
    __syncthreads();

    // per-bucket insertion sort (segment = [bstart[b]-bcnt[b], bstart[b]))
    for (int b = t; b < NN; b += 1024) {
        int c = bcnt[b];
        if (c > 1) {
            int s = bstart[b] - c;
            for (int a = 1; a < c; a++) {
                u64 v = keys[s + a];
                int q = a - 1;
                while (q >= 0 && keys[s + q] > v) { keys[s + q + 1] = keys[s + q]; q--; }
                keys[s + q + 1] = v;
            }
        }
    }
    __syncthreads();

    // inverse permutation
    #pragma unroll
    for (int k = 0; k < 4; k++) {
        int i = base + k;
        g_rank[(int)(keys[i] & 0xFFFFFFFFu)] = i;
    }
}

// prep as its own tiny multi-block body (launched in SAME kernel via blocks>=1 is
// messy with labels; instead do prep as a separate concurrent-friendly kernel is
// NOT possible without a launch. So: prep is folded into k_sortprep blocks>=1
// above, but it needs labels. We re-do prep here properly with labels.
__global__ __launch_bounds__(256) void k_prep(
    const float* __restrict__ pb, const int* __restrict__ pl)
{
    int idx = blockIdx.x * 256 + threadIdx.x;
    if (idx >= NN) return;
    float b0 = pb[idx*9 + 0];
    float b1 = pb[idx*9 + 1];
    float b3 = pb[idx*9 + 3];
    float b4 = pb[idx*9 + 4];
    float b6 = pb[idx*9 + 6];
    float ang = b6 - floorf(b6 / PI_F + 0.5f) * PI_F;
    bool  sw  = fabsf(ang) >= QPI_F;
    float dx  = sw ? b4 : b3;
    float dy  = sw ? b3 : b4;
    float4 bv;
    bv.x = b0 - dx * 0.5f;
    bv.y = b1 - dy * 0.5f;
    bv.z = b0 + dx * 0.5f;
    bv.w = b1 + dy * 0.5f;
    g_bev[idx]  = bv;
    g_area[idx] = dx * dy;
    int lab = pl[idx];
    int cx = (int)floorf((b0 + 70.0f) * (1.0f / 4.5f)); cx = min(max(cx, 0), NX-1);
    int cy = (int)floorf((b1 + 40.0f) * (1.0f / 4.5f)); cy = min(max(cy, 0), NY-1);
    int cell = (lab * NY + cy) * NX + cx;
    g_cellid[idx] = cell;
    int pos = atomicAdd(&g_cellcnt[cell], 1);
    if (pos < CAPC) g_cellbox[cell*CAPC + pos] = (u16)idx;
}

// ============ 2) build pred/succ (sorted space) + gather outputs ============
__global__ __launch_bounds__(256) void k_build(
    const float* __restrict__ pb, const float* __restrict__ ps,
    const int* __restrict__ pl, float* __restrict__ out)
{
    int idx = blockIdx.x * 256 + threadIdx.x;   // original index
    if (idx >= NN) return;
    int ri = g_rank[idx];

    // gather outputs (reads coalesced by idx, scattered writes over 16 SMs)
    float b[9];
    #pragma unroll
    for (int c = 0; c < 9; c++) b[c] = pb[idx*9 + c];
    #pragma unroll
    for (int c = 0; c < 7; c++) { g_b7[ri*7 + c] = b[c]; out[ri*9 + c] = b[c]; }
    out[ri*9 + 7] = b[7];
    out[ri*9 + 8] = b[8];
    out[NN*9  + ri] = ps[idx];
    out[NN*10 + ri] = (float)pl[idx];

    // pair tests in original space; classify by rank
    float4 a = g_bev[idx];
    float aa = g_area[idx];
    int cell = g_cellid[idx];
    int cx = cell % NX, cy = (cell / NX) % NY, lab = cell / (NX * NY);
    int np = 0, ns = 0;
    for (int dy = -1; dy <= 1; dy++) {
        int yy = cy + dy; if (yy < 0 || yy >= NY) continue;
        for (int dx = -1; dx <= 1; dx++) {
            int xx = cx + dx; if (xx < 0 || xx >= NX) continue;
            int c2 = (lab * NY + yy) * NX + xx;
            int cnt2 = min(g_cellcnt[c2], CAPC);
            for (int p = 0; p < cnt2; p++) {
                int j = g_cellbox[c2*CAPC + p];
                if (j == idx) continue;
                float4 bb = g_bev[j];
                float ix = fminf(a.z, bb.z) - fmaxf(a.x, bb.x);
                float iy = fminf(a.w, bb.w) - fmaxf(a.y, bb.y);
                float inter = fmaxf(ix, 0.0f) * fmaxf(iy, 0.0f);
                float uni   = aa + g_area[j] - inter;
                if (inter > IOUT * fmaxf(uni, 1e-6f)) {
                    int rj = g_rank[j];
                    if (rj < ri) { if (np < CAP) g_pred[ri*CAP + np++] = (u16)rj; }
                    else         { if (ns < CAP) g_succ[ri*CAP + ns++] = (u16)rj; }
                }
            }
        }
    }
    // sort both ascending (pred: enables early-exit fixpoint; succ: member order)
    for (int a2 = 1; a2 < np; a2++) {
        u16 v = g_pred[ri*CAP + a2];
        int q = a2 - 1;
        while (q >= 0 && g_pred[ri*CAP + q] > v) { g_pred[ri*CAP + q + 1] = g_pred[ri*CAP + q]; q--; }
        g_pred[ri*CAP + q + 1] = v;
    }
    for (int a2 = 1; a2 < ns; a2++) {
        u16 v = g_succ[ri*CAP + a2];
        int q = a2 - 1;
        while (q >= 0 && g_succ[ri*CAP + q] > v) { g_succ[ri*CAP + q + 1] = g_succ[ri*CAP + q]; q--; }
        g_succ[ri*CAP + q + 1] = v;
    }
    g_npred[ri] = np;
    g_nsucc[ri] = ns;
}

// ============ 3) single-block fixpoint with ordered early-exit scan ============
__global__ __launch_bounds__(1024) void k_fix(float* __restrict__ out) {
    __shared__ u8  sts[NN];
    __shared__ u16 fl0[NN], fl1[NN];
    __shared__ int s_nf, s_nn;
    volatile u8* st = sts;
    const int t = threadIdx.x;
    const int vt = g_vt;

    for (int i = t; i < NN; i += 1024) sts[i] = (i < vt) ? 0 : 3;
    for (int i = t; i < vt; i += 1024) fl0[i] = (u16)i;
    if (t == 0) s_nf = vt;
    __syncthreads();

    u16* cur = fl0; u16* nxt = fl1;
    for (int round = 0; round < NN; round++) {
        int nf = s_nf;
        if (nf <= 0) break;
        if (t == 0) s_nn = 0;
        __syncthreads();
        for (int k = t; k < nf; k += 1024) {
            int i = cur[k];
            int np = g_npred[i];
            const u16* pr = &g_pred[i*CAP];
            int res = 1;       // kept unless blocked
            u16 sb = (u16)i;
            for (int p = 0; p < np; p++) {
                u16 j = pr[p];
                u8 s = st[j];
                if (s == 0) { res = 0; break; }          // unresolved pred -> wait
                if (s == 1) { res = 2; sb = j; break; }  // first kept pred (min) -> suppressed
                // s>=2: suppressed/invalid, keep scanning
            }
            if (res == 0) { int pos = atomicAdd(&s_nn, 1); nxt[pos] = (u16)i; }
            else { st[i] = (u8)res; g_sby[i] = sb; }
        }
        __syncthreads();
        if (t == 0) s_nf = s_nn;
        u16* tmpp = cur; cur = nxt; nxt = tmpp;
        __syncthreads();
    }

    // publish
    for (int i = t; i < NN; i += 1024) {
        u8 s = sts[i];
        g_sts[i] = s;
        out[NN*11 + i] = (s == 1) ? 1.0f : 0.0f;
        if (s == 3) g_sby[i] = 0xFFFF;
    }
}

// ============ 4) merge MLP + re-zero cell counts for next run ============
__global__ __launch_bounds__(256) void k_merge(
    const float* __restrict__ w1, const float* __restrict__ b1,
    const float* __restrict__ w2, const float* __restrict__ b2,
    const float* __restrict__ w3, const float* __restrict__ b3,
    float* __restrict__ out)
{
    __shared__ float s_w1[MM*HH], s_w2[HH*HH], s_w3[HH], s_b1[HH], s_b2[HH], s_b3;
    const int t = threadIdx.x;
    for (int k = t; k < MM*HH; k += 256) s_w1[k] = w1[k];
    for (int k = t; k < HH*HH; k += 256) s_w2[k] = w2[k];
    if (t < HH) { s_w3[t] = w3[t]; s_b1[t] = b1[t]; s_b2[t] = b2[t]; }
    if (t == 0) s_b3 = b3[0];
    // re-zero cell counters for the next graph replay (nothing reads them after k_build)
    if (blockIdx.x < 7) {
        int c = blockIdx.x * 256 + t;
        if (c < NCELL) g_cellcnt[c] = 0;
    }
    __syncthreads();

    int gt = blockIdx.x * 256 + t;
    int i = gt >> 3;
    int c = gt & 7;
    if (c >= 7 || i >= NN) return;
    if (g_sts[i] != 1) return;

    // rebuild member list (succ asc; member iff suppressed-by == i)
    int ns = g_nsucc[i];
    u16 mem[MM];
    mem[0] = (u16)i;
    int cnt = 1, total = 1;
    for (int a = 0; a < ns; a++) {
        int j = g_succ[i*CAP + a];
        if ((int)g_sby[j] == i) { total++; if (cnt < MM) mem[cnt++] = (u16)j; }
    }
    if (total <= 1) return;   // baseline row already written by k_build

    float xv[MM];
    #pragma unroll
    for (int m = 0; m < MM; m++) if (m < cnt) xv[m] = g_b7[(int)mem[m]*7 + c];

    float h1[HH];
    #pragma unroll
    for (int h = 0; h < HH; h++) h1[h] = s_b1[h];
    #pragma unroll
    for (int m = 0; m < MM; m++) {
        if (m < cnt) {
            float v = xv[m];
            #pragma unroll
            for (int h = 0; h < HH; h++) h1[h] += v * s_w1[m*HH + h];
        }
    }
    #pragma unroll
    for (int h = 0; h < HH; h++) h1[h] = fmaxf(h1[h], 0.0f);
    float h2[HH];
    #pragma unroll
    for (int q = 0; q < HH; q++) h2[q] = s_b2[q];
    #pragma unroll
    for (int h = 0; h < HH; h++) {
        float v = h1[h];
        #pragma unroll
        for (int q = 0; q < HH; q++) h2[q] += v * s_w2[h*HH + q];
    }
    float acc = s_b3;
    #pragma unroll
    for (int q = 0; q < HH; q++) acc += fmaxf(h2[q], 0.0f) * s_w3[q];

    if (c >= 3 && c <= 5) acc = fmaxf(acc, 1e-5f);
    out[i*9 + c] = acc;
}

extern "C" void kernel_launch(void* const* d_in, const int* in_sizes, int n_in,
                              void* d_out, int out_size) {
    const float* pb = (const float*)d_in[0];
    const float* ps = (const float*)d_in[1];
    const int*   pl = (const int*)  d_in[2];
    const float* w1 = (const float*)d_in[3];
    const float* b1 = (const float*)d_in[4];
    const float* w2 = (const float*)d_in[5];
    const float* b2 = (const float*)d_in[6];
    const float* w3 = (const float*)d_in[7];
    const float* b3 = (const float*)d_in[8];
    float* out = (float*)d_out;

    cudaFuncSetAttribute(k_sortprep, cudaFuncAttributeMaxDynamicSharedMemorySize, SMEM_A);
    // k_prep and k_sortprep(block 0) are independent; issue prep first (small),
    // then sort — both before k_build which needs both.
    k_prep<<<16, 256>>>(pb, pl);
    k_sortprep<<<1, 1024, SMEM_A>>>(ps, pb);
    k_build<<<16, 256>>>(pb, ps, pl, out);
    k_fix<<<1, 1024>>>(out);
    k_merge<<<128, 256>>>(w1, b1, w2, b2, w3, b3, out);
}